// round 4
// baseline (speedup 1.0000x reference)
#include <cuda_runtime.h>

// Problem constants (from reference: N=100000, E=1600000, ND=ED=OD=32)
#define NODES_MAX 100000
#define SNSE_ELEMS (NODES_MAX * 64)

// Scratch: per-node sums of gathered node features (cols 0..31) and edge
// features (cols 32..63), plus float degree. Device globals (no allocation).
__device__ float g_snse[SNSE_ELEMS];
__device__ float g_deg[NODES_MAX];

// ---------------------------------------------------------------------------
// Kernel 1: zero the accumulators (graph replays must start clean).
// ---------------------------------------------------------------------------
__global__ void mp_zero_kernel(int n_nodes) {
    int stride = gridDim.x * blockDim.x;
    int i = blockIdx.x * blockDim.x + threadIdx.x;
    float4 z4 = make_float4(0.f, 0.f, 0.f, 0.f);
    float4* snse4 = reinterpret_cast<float4*>(g_snse);
    int total4 = n_nodes * 16;               // 64 floats = 16 float4 per node
    for (int k = i; k < total4; k += stride) snse4[k] = z4;
    for (int k = i; k < n_nodes; k += stride) g_deg[k] = 0.f;
}

// ---------------------------------------------------------------------------
// Kernel 2: edge scatter. The message Linear commutes with the sum-reduce,
// so we only scatter raw features: snse[dst] += [node_x[src], edge_x[e]].
// 16 threads per edge, each does one red.global.add.v4.f32 (16B atomic).
// ---------------------------------------------------------------------------
__global__ void mp_scatter_kernel(const float4* __restrict__ node_x4,
                                  const float4* __restrict__ edge_x4,
                                  const int* __restrict__ src,
                                  const int* __restrict__ dst,
                                  int n_edges) {
    int idx = blockIdx.x * blockDim.x + threadIdx.x;
    int e = idx >> 4;
    if (e >= n_edges) return;
    int c = idx & 15;

    int d = __ldg(dst + e);
    float4 v;
    if (c < 8) {
        int s = __ldg(src + e);
        v = __ldg(node_x4 + (size_t)s * 8 + c);        // node_x row: L2-resident
    } else {
        v = __ldg(edge_x4 + (size_t)e * 8 + (c - 8));  // edge_x: streaming DRAM
    }

    float* p = g_snse + (size_t)d * 64 + c * 4;        // 16B-aligned
    asm volatile("red.global.add.v4.f32 [%0], {%1,%2,%3,%4};"
                 :: "l"(p), "f"(v.x), "f"(v.y), "f"(v.z), "f"(v.w)
                 : "memory");

    if (c == 0) atomicAdd(g_deg + d, 1.0f);            // RED (result unused)
}

// ---------------------------------------------------------------------------
// Kernel 3: per-node fused epilogue. Warp-per-node:
//   agg = snse @ W_pre + deg*b_pre          (64 outputs, 2 per lane)
//   z   = deg>0 ? relu(agg) : z_init
//   h   = relu([node_x, z] @ W_upd + b_upd) (32 outputs, 1 per lane)
// Weights live in shared memory; row-vector operands broadcast via shuffles.
// ---------------------------------------------------------------------------
__global__ void __launch_bounds__(256)
mp_node_kernel(const float* __restrict__ node_x,
               const float* __restrict__ z_init,
               const float* __restrict__ W_pre,   // [64,64] row-major
               const float* __restrict__ b_pre,   // [64]
               const float* __restrict__ W_upd,   // [96,32] row-major
               const float* __restrict__ b_upd,   // [32]
               float* __restrict__ out,           // [N,32]
               int n_nodes) {
    __shared__ float sWp[64 * 64];
    __shared__ float sWu[96 * 32];
    __shared__ float sbp[64];
    __shared__ float sbu[32];

    for (int k = threadIdx.x; k < 64 * 64; k += blockDim.x) sWp[k] = W_pre[k];
    for (int k = threadIdx.x; k < 96 * 32; k += blockDim.x) sWu[k] = W_upd[k];
    if (threadIdx.x < 64) sbp[threadIdx.x] = b_pre[threadIdx.x];
    if (threadIdx.x < 32) sbu[threadIdx.x] = b_upd[threadIdx.x];
    __syncthreads();

    int n = (blockIdx.x * blockDim.x + threadIdx.x) >> 5;   // warp id = node id
    if (n >= n_nodes) return;                               // uniform per warp
    int lane = threadIdx.x & 31;

    float s0 = g_snse[(size_t)n * 64 + lane];        // summed node feats
    float s1 = g_snse[(size_t)n * 64 + 32 + lane];   // summed edge feats
    float dg = g_deg[n];

    // agg = snse_row @ W_pre + deg * b_pre   (lane j owns outputs j, j+32)
    float a0 = dg * sbp[lane];
    float a1 = dg * sbp[32 + lane];
#pragma unroll
    for (int i = 0; i < 32; i++) {
        float si = __shfl_sync(0xffffffffu, s0, i);
        a0 = fmaf(si, sWp[i * 64 + lane], a0);
        a1 = fmaf(si, sWp[i * 64 + 32 + lane], a1);
    }
#pragma unroll
    for (int i = 0; i < 32; i++) {
        float si = __shfl_sync(0xffffffffu, s1, i);
        a0 = fmaf(si, sWp[(32 + i) * 64 + lane], a0);
        a1 = fmaf(si, sWp[(32 + i) * 64 + 32 + lane], a1);
    }

    float z0, z1;
    if (dg > 0.f) {
        z0 = fmaxf(a0, 0.f);
        z1 = fmaxf(a1, 0.f);
    } else {
        z0 = z_init[(size_t)n * 64 + lane];
        z1 = z_init[(size_t)n * 64 + 32 + lane];
    }

    // h = relu([node_x, z] @ W_upd + b_upd)   (lane j owns output j)
    float x = node_x[(size_t)n * 32 + lane];
    float h = sbu[lane];
#pragma unroll
    for (int i = 0; i < 32; i++)
        h = fmaf(__shfl_sync(0xffffffffu, x, i), sWu[i * 32 + lane], h);
#pragma unroll
    for (int i = 0; i < 32; i++)
        h = fmaf(__shfl_sync(0xffffffffu, z0, i), sWu[(32 + i) * 32 + lane], h);
#pragma unroll
    for (int i = 0; i < 32; i++)
        h = fmaf(__shfl_sync(0xffffffffu, z1, i), sWu[(64 + i) * 32 + lane], h);

    out[(size_t)n * 32 + lane] = fmaxf(h, 0.f);
}

// ---------------------------------------------------------------------------
// Launch: inputs per metadata order:
// node_x, edge_x, z_init, W_pre, b_pre, W_upd, b_upd, src, dst
// ---------------------------------------------------------------------------
extern "C" void kernel_launch(void* const* d_in, const int* in_sizes, int n_in,
                              void* d_out, int out_size) {
    const float* node_x = (const float*)d_in[0];
    const float* edge_x = (const float*)d_in[1];
    const float* z_init = (const float*)d_in[2];
    const float* W_pre  = (const float*)d_in[3];
    const float* b_pre  = (const float*)d_in[4];
    const float* W_upd  = (const float*)d_in[5];
    const float* b_upd  = (const float*)d_in[6];
    const int*   src    = (const int*)d_in[7];
    const int*   dst    = (const int*)d_in[8];
    float* out = (float*)d_out;

    int n_nodes = in_sizes[0] / 32;   // 100000
    int n_edges = in_sizes[7];        // 1600000

    mp_zero_kernel<<<1024, 256>>>(n_nodes);

    int scatter_threads = n_edges * 16;
    mp_scatter_kernel<<<(scatter_threads + 255) / 256, 256>>>(
        (const float4*)node_x, (const float4*)edge_x, src, dst, n_edges);

    int node_threads = n_nodes * 32;
    mp_node_kernel<<<(node_threads + 255) / 256, 256>>>(
        node_x, z_init, W_pre, b_pre, W_upd, b_upd, out, n_nodes);
}

// round 5
// speedup vs baseline: 1.1330x; 1.1330x over previous
#include <cuda_runtime.h>

// Problem constants (N=100000, E=1600000, ND=ED=OD=32)
#define NODES_MAX 100000
#define EDGES_MAX 1600000
#define SCAN_T 1024

// Device-global scratch (no allocations allowed).
__device__ int g_count[NODES_MAX];     // in-degree histogram
__device__ int g_rowtmp[NODES_MAX];    // block-local exclusive scan
__device__ int g_row[NODES_MAX];       // CSR row offsets
__device__ int g_cursor[NODES_MAX];    // permutation cursors
__device__ int g_part[256];            // per-block scan partials
__device__ int g_esrc[EDGES_MAX];      // sorted-by-dst: src node id
__device__ int g_eeid[EDGES_MAX];      // sorted-by-dst: original edge id

// ---------------------------------------------------------------------------
// 1. zero histogram
// ---------------------------------------------------------------------------
__global__ void mp_zero_kernel(int n_nodes) {
    int i = blockIdx.x * blockDim.x + threadIdx.x;
    if (i < n_nodes) g_count[i] = 0;
}

// ---------------------------------------------------------------------------
// 2. in-degree histogram (RED.ADD, result unused)
// ---------------------------------------------------------------------------
__global__ void mp_hist_kernel(const int* __restrict__ dst, int n_edges) {
    int e = blockIdx.x * blockDim.x + threadIdx.x;
    if (e < n_edges) atomicAdd(&g_count[__ldg(dst + e)], 1);
}

// ---------------------------------------------------------------------------
// 3a. block-wise exclusive scan of g_count -> g_rowtmp, block sums -> g_part
// ---------------------------------------------------------------------------
__global__ void mp_scan1_kernel(int n_nodes) {
    __shared__ int sh[SCAN_T];
    int t = threadIdx.x, b = blockIdx.x;
    int idx = b * SCAN_T + t;
    int v = (idx < n_nodes) ? g_count[idx] : 0;
    sh[t] = v;
    __syncthreads();
    for (int off = 1; off < SCAN_T; off <<= 1) {
        int x = 0;
        if (t >= off) x = sh[t - off];
        __syncthreads();
        if (t >= off) sh[t] += x;
        __syncthreads();
    }
    if (idx < n_nodes) g_rowtmp[idx] = sh[t] - v;   // exclusive
    if (t == SCAN_T - 1) g_part[b] = sh[t];          // block total
}

// 3b. exclusive scan of g_part (single block; nb <= SCAN_T)
__global__ void mp_scan2_kernel(int nb) {
    __shared__ int sh[SCAN_T];
    int t = threadIdx.x;
    int v = (t < nb) ? g_part[t] : 0;
    sh[t] = v;
    __syncthreads();
    for (int off = 1; off < SCAN_T; off <<= 1) {
        int x = 0;
        if (t >= off) x = sh[t - off];
        __syncthreads();
        if (t >= off) sh[t] += x;
        __syncthreads();
    }
    if (t < nb) g_part[t] = sh[t] - v;
}

// 3c. combine -> g_row, and init cursors
__global__ void mp_scan3_kernel(int n_nodes) {
    int idx = blockIdx.x * blockDim.x + threadIdx.x;
    if (idx < n_nodes) {
        int r = g_rowtmp[idx] + g_part[blockIdx.x * blockDim.x / SCAN_T == 0
                                           ? idx / SCAN_T : idx / SCAN_T];
        g_row[idx] = r;
        g_cursor[idx] = r;
    }
}

// ---------------------------------------------------------------------------
// 4. permutation: scatter (src, eid) into dst-sorted order. Only int atomics.
// ---------------------------------------------------------------------------
__global__ void mp_permute_kernel(const int* __restrict__ src,
                                  const int* __restrict__ dst,
                                  int n_edges) {
    int e = blockIdx.x * blockDim.x + threadIdx.x;
    if (e >= n_edges) return;
    int d = __ldg(dst + e);
    int pos = atomicAdd(&g_cursor[d], 1);
    g_esrc[pos] = __ldg(src + e);
    g_eeid[pos] = e;
}

// ---------------------------------------------------------------------------
// 5. fused gather + epilogue. Warp per node:
//    s0 = sum node_x[src[e]],  s1 = sum edge_x[e]   over in-edges (CSR walk)
//    agg = [s0,s1] @ W_pre + deg*b_pre ; z = deg>0 ? relu(agg) : z_init
//    h   = relu([node_x, z] @ W_upd + b_upd)
// ---------------------------------------------------------------------------
__global__ void __launch_bounds__(256)
mp_gather_kernel(const float* __restrict__ node_x,
                 const float* __restrict__ edge_x,
                 const float* __restrict__ z_init,
                 const float* __restrict__ W_pre,   // [64,64]
                 const float* __restrict__ b_pre,   // [64]
                 const float* __restrict__ W_upd,   // [96,32]
                 const float* __restrict__ b_upd,   // [32]
                 float* __restrict__ out,           // [N,32]
                 int n_nodes) {
    __shared__ float sWp[64 * 64];
    __shared__ float sWu[96 * 32];
    __shared__ float sbp[64];
    __shared__ float sbu[32];

    for (int k = threadIdx.x; k < 64 * 64; k += blockDim.x) sWp[k] = W_pre[k];
    for (int k = threadIdx.x; k < 96 * 32; k += blockDim.x) sWu[k] = W_upd[k];
    if (threadIdx.x < 64) sbp[threadIdx.x] = b_pre[threadIdx.x];
    if (threadIdx.x < 32) sbu[threadIdx.x] = b_upd[threadIdx.x];
    __syncthreads();

    int n = (blockIdx.x * blockDim.x + threadIdx.x) >> 5;   // warp = node
    if (n >= n_nodes) return;                               // uniform per warp
    int lane = threadIdx.x & 31;

    int start = g_row[n];
    int deg   = g_count[n];

    float s0 = 0.f, s1 = 0.f;
    for (int base = 0; base < deg; base += 32) {
        int m = deg - base;
        if (m > 32) m = 32;
        int sidx = 0, eidx = 0;
        if (lane < m) {
            sidx = g_esrc[start + base + lane];
            eidx = g_eeid[start + base + lane];
        }
        int j = 0;
        for (; j + 4 <= m; j += 4) {   // 4-wide unroll for MLP
            int s_0 = __shfl_sync(0xffffffffu, sidx, j);
            int e_0 = __shfl_sync(0xffffffffu, eidx, j);
            int s_1 = __shfl_sync(0xffffffffu, sidx, j + 1);
            int e_1 = __shfl_sync(0xffffffffu, eidx, j + 1);
            int s_2 = __shfl_sync(0xffffffffu, sidx, j + 2);
            int e_2 = __shfl_sync(0xffffffffu, eidx, j + 2);
            int s_3 = __shfl_sync(0xffffffffu, sidx, j + 3);
            int e_3 = __shfl_sync(0xffffffffu, eidx, j + 3);
            float n0 = __ldg(node_x + (size_t)s_0 * 32 + lane);
            float x0 = __ldg(edge_x + (size_t)e_0 * 32 + lane);
            float n1 = __ldg(node_x + (size_t)s_1 * 32 + lane);
            float x1 = __ldg(edge_x + (size_t)e_1 * 32 + lane);
            float n2 = __ldg(node_x + (size_t)s_2 * 32 + lane);
            float x2 = __ldg(edge_x + (size_t)e_2 * 32 + lane);
            float n3 = __ldg(node_x + (size_t)s_3 * 32 + lane);
            float x3 = __ldg(edge_x + (size_t)e_3 * 32 + lane);
            s0 += (n0 + n1) + (n2 + n3);
            s1 += (x0 + x1) + (x2 + x3);
        }
        for (; j < m; j++) {
            int s_0 = __shfl_sync(0xffffffffu, sidx, j);
            int e_0 = __shfl_sync(0xffffffffu, eidx, j);
            s0 += __ldg(node_x + (size_t)s_0 * 32 + lane);
            s1 += __ldg(edge_x + (size_t)e_0 * 32 + lane);
        }
    }

    float dg = (float)deg;

    // agg = [s0,s1] @ W_pre + deg * b_pre  (lane j owns outputs j, j+32)
    float a0 = dg * sbp[lane];
    float a1 = dg * sbp[32 + lane];
#pragma unroll
    for (int i = 0; i < 32; i++) {
        float si = __shfl_sync(0xffffffffu, s0, i);
        a0 = fmaf(si, sWp[i * 64 + lane], a0);
        a1 = fmaf(si, sWp[i * 64 + 32 + lane], a1);
    }
#pragma unroll
    for (int i = 0; i < 32; i++) {
        float si = __shfl_sync(0xffffffffu, s1, i);
        a0 = fmaf(si, sWp[(32 + i) * 64 + lane], a0);
        a1 = fmaf(si, sWp[(32 + i) * 64 + 32 + lane], a1);
    }

    float z0, z1;
    if (deg > 0) {
        z0 = fmaxf(a0, 0.f);
        z1 = fmaxf(a1, 0.f);
    } else {
        z0 = z_init[(size_t)n * 64 + lane];
        z1 = z_init[(size_t)n * 64 + 32 + lane];
    }

    // h = relu([node_x, z] @ W_upd + b_upd)
    float x = node_x[(size_t)n * 32 + lane];
    float h = sbu[lane];
#pragma unroll
    for (int i = 0; i < 32; i++)
        h = fmaf(__shfl_sync(0xffffffffu, x, i), sWu[i * 32 + lane], h);
#pragma unroll
    for (int i = 0; i < 32; i++)
        h = fmaf(__shfl_sync(0xffffffffu, z0, i), sWu[(32 + i) * 32 + lane], h);
#pragma unroll
    for (int i = 0; i < 32; i++)
        h = fmaf(__shfl_sync(0xffffffffu, z1, i), sWu[(64 + i) * 32 + lane], h);

    out[(size_t)n * 32 + lane] = fmaxf(h, 0.f);
}

// ---------------------------------------------------------------------------
// Launch. Inputs: node_x, edge_x, z_init, W_pre, b_pre, W_upd, b_upd, src, dst
// ---------------------------------------------------------------------------
extern "C" void kernel_launch(void* const* d_in, const int* in_sizes, int n_in,
                              void* d_out, int out_size) {
    const float* node_x = (const float*)d_in[0];
    const float* edge_x = (const float*)d_in[1];
    const float* z_init = (const float*)d_in[2];
    const float* W_pre  = (const float*)d_in[3];
    const float* b_pre  = (const float*)d_in[4];
    const float* W_upd  = (const float*)d_in[5];
    const float* b_upd  = (const float*)d_in[6];
    const int*   src    = (const int*)d_in[7];
    const int*   dst    = (const int*)d_in[8];
    float* out = (float*)d_out;

    int n_nodes = in_sizes[0] / 32;   // 100000
    int n_edges = in_sizes[7];        // 1600000
    int nb = (n_nodes + SCAN_T - 1) / SCAN_T;   // 98 scan blocks

    mp_zero_kernel<<<(n_nodes + 255) / 256, 256>>>(n_nodes);
    mp_hist_kernel<<<(n_edges + 255) / 256, 256>>>(dst, n_edges);
    mp_scan1_kernel<<<nb, SCAN_T>>>(n_nodes);
    mp_scan2_kernel<<<1, SCAN_T>>>(nb);
    mp_scan3_kernel<<<nb, SCAN_T>>>(n_nodes);
    mp_permute_kernel<<<(n_edges + 255) / 256, 256>>>(src, dst, n_edges);
    mp_gather_kernel<<<(n_nodes * 32 + 255) / 256, 256>>>(
        node_x, edge_x, z_init, W_pre, b_pre, W_upd, b_upd, out, n_nodes);
}